// round 14
// baseline (speedup 1.0000x reference)
#include <cuda_runtime.h>
#include <cuda_bf16.h>
#include <cstdint>

#define B__   256
#define NTOK  196
#define CDIM  256
#define NH    8
#define HDIM  32
#define MROWS (B__ * NTOK)          // 50176 = 392*128
#define KEXT  768                   // 3*256 split-bf16 K
#define QSCALE 0.17677669529663687f // 1/sqrt(32)

typedef unsigned long long ull;

// ---------------- scratch (device globals) ----------------
__device__ float g_q[MROWS * CDIM];
__device__ float g_k[MROWS * CDIM];
__device__ float g_v[MROWS * CDIM];
__device__ float g_bm[NH * NTOK * NTOK];             // bias gathered per head
__device__ __nv_bfloat16 g_xb[(size_t)MROWS * KEXT]; // x split  [Ah, Al, Ah]
__device__ __nv_bfloat16 g_ob[(size_t)MROWS * KEXT]; // attn-out split
__device__ __nv_bfloat16 g_wq[768 * KEXT];           // qkv_w split [Bh, Bh, Bl]
__device__ __nv_bfloat16 g_wp[256 * KEXT];           // proj_w split

// ---------------- small PTX helpers ----------------
__device__ __forceinline__ uint32_t s2u(const void* p) {
    return (uint32_t)__cvta_generic_to_shared(p);
}
#define CP16(dst, src) \
    asm volatile("cp.async.ca.shared.global [%0], [%1], 16;" :: "r"(dst), "l"(src))
#define CP_COMMIT() asm volatile("cp.async.commit_group;" ::: "memory")
#define CP_WAIT(n)  asm volatile("cp.async.wait_group %0;" :: "n"(n) : "memory")

#define LDSM4(r0, r1, r2, r3, addr) \
    asm volatile("ldmatrix.sync.aligned.m8n8.x4.shared.b16 {%0,%1,%2,%3}, [%4];" \
                 : "=r"(r0), "=r"(r1), "=r"(r2), "=r"(r3) : "r"(addr))
#define LDSM4T(r0, r1, r2, r3, addr) \
    asm volatile("ldmatrix.sync.aligned.m8n8.x4.trans.shared.b16 {%0,%1,%2,%3}, [%4];" \
                 : "=r"(r0), "=r"(r1), "=r"(r2), "=r"(r3) : "r"(addr))

#define MMA16816(d, a, b0, b1) \
    asm volatile("mma.sync.aligned.m16n8k16.row.col.f32.bf16.bf16.f32 " \
                 "{%0,%1,%2,%3}, {%4,%5,%6,%7}, {%8,%9}, {%0,%1,%2,%3};" \
                 : "+f"((d)[0]), "+f"((d)[1]), "+f"((d)[2]), "+f"((d)[3]) \
                 : "r"((a)[0]), "r"((a)[1]), "r"((a)[2]), "r"((a)[3]), \
                   "r"(b0), "r"(b1))

// pack two f32 into bf16x2: first arg -> low half
__device__ __forceinline__ uint32_t bfpack(float lo, float hi) {
    uint32_t r;
    asm("cvt.rn.bf16x2.f32 %0, %1, %2;" : "=r"(r) : "f"(hi), "f"(lo));
    return r;
}
// split float2 into (hi, lo) bf16x2 pair (lo = residual)
__device__ __forceinline__ void split2(float2 v, uint32_t& hi, uint32_t& lo) {
    hi = bfpack(v.x, v.y);
    const float f0 = __uint_as_float(hi << 16);
    const float f1 = __uint_as_float(hi & 0xffff0000u);
    lo = bfpack(v.x - f0, v.y - f1);
}

// ---------------- split-bf16 conversion ----------------
__device__ __forceinline__ uint32_t pk2(float x, float y) {
    __nv_bfloat162 t = __float22bfloat162_rn(make_float2(x, y));
    return *(uint32_t*)&t;
}
// activations: [M][256] f32 -> [M][768] bf16 as {hi, lo, hi}
__global__ __launch_bounds__(256) void conv_act(const float* __restrict__ src,
                                                __nv_bfloat16* __restrict__ dst) {
    int i = blockIdx.x * 256 + threadIdx.x;       // float4 index, total MROWS*64
    float4 v = ((const float4*)src)[i];
    int row = i >> 6, c = (i & 63) << 2;
    __nv_bfloat16 hx = __float2bfloat16(v.x), hy = __float2bfloat16(v.y);
    __nv_bfloat16 hz = __float2bfloat16(v.z), hw = __float2bfloat16(v.w);
    float lx = v.x - __bfloat162float(hx), ly = v.y - __bfloat162float(hy);
    float lz = v.z - __bfloat162float(hz), lw = v.w - __bfloat162float(hw);
    uint2 hi; hi.x = pk2(__bfloat162float(hx), __bfloat162float(hy));
              hi.y = pk2(__bfloat162float(hz), __bfloat162float(hw));
    uint2 lo; lo.x = pk2(lx, ly); lo.y = pk2(lz, lw);
    __nv_bfloat16* base = dst + (size_t)row * KEXT + c;
    *(uint2*)(base)       = hi;
    *(uint2*)(base + 256) = lo;
    *(uint2*)(base + 512) = hi;
}
// weights: [N][256] f32 -> [N][768] bf16 as {hi, hi, lo}
__global__ __launch_bounds__(256) void conv_wgt(const float* __restrict__ src,
                                                __nv_bfloat16* __restrict__ dst) {
    int i = blockIdx.x * 256 + threadIdx.x;
    float4 v = ((const float4*)src)[i];
    int row = i >> 6, c = (i & 63) << 2;
    __nv_bfloat16 hx = __float2bfloat16(v.x), hy = __float2bfloat16(v.y);
    __nv_bfloat16 hz = __float2bfloat16(v.z), hw = __float2bfloat16(v.w);
    float lx = v.x - __bfloat162float(hx), ly = v.y - __bfloat162float(hy);
    float lz = v.z - __bfloat162float(hz), lw = v.w - __bfloat162float(hw);
    uint2 hi; hi.x = pk2(__bfloat162float(hx), __bfloat162float(hy));
              hi.y = pk2(__bfloat162float(hz), __bfloat162float(hw));
    uint2 lo; lo.x = pk2(lx, ly); lo.y = pk2(lz, lw);
    __nv_bfloat16* base = dst + (size_t)row * KEXT + c;
    *(uint2*)(base)       = hi;
    *(uint2*)(base + 256) = hi;
    *(uint2*)(base + 512) = lo;
}

// bias gather precompute: g_bm[h][n][m] = bias_table[rel_index[n*196+m]][h]
__global__ __launch_bounds__(256) void bias_pre(const float* __restrict__ bt,
                                                const int* __restrict__ ri) {
    int i = blockIdx.x * 256 + threadIdx.x;
    if (i < NTOK * NTOK) {
        const int idx = ri[i];
#pragma unroll
        for (int h = 0; h < NH; h++)
            g_bm[h * (NTOK * NTOK) + i] = bt[idx * NH + h];
    }
}

// ---------------- HMMA bf16 GEMM (unchanged from R7) ----------------
#define BK     32
#define LDS_S  40
#define NSTG   (KEXT / BK)          // 24
#define STAGEF (128 * LDS_S)
#define GSMEM  (4 * STAGEF * 2 * 2) // 81920 bytes

template <int MODE>
__global__ __launch_bounds__(256, 2) void hmma_gemm(const float* __restrict__ bias,
                                                    float* __restrict__ out) {
    extern __shared__ __align__(16) __nv_bfloat16 smb[];
    __nv_bfloat16* As = smb;
    __nv_bfloat16* Bs = smb + 4 * STAGEF;

    const int tid = threadIdx.x, lane = tid & 31, wid = tid >> 5;
    const int nt = blockIdx.x;
    const int rowBase = blockIdx.y << 7;
    const int colBase = nt << 7;

    const __nv_bfloat16* Ag = ((MODE == 0) ? g_xb : g_ob) + (size_t)rowBase * KEXT;
    const __nv_bfloat16* Bg = ((MODE == 0) ? g_wq : g_wp) + (size_t)colBase * KEXT;

    const int c0r = tid >> 2, c0c = (tid & 3) << 3;
    const int c1r = (tid + 256) >> 2, c1c = c0c;

#define LOADSTAGE(s) do { \
    const int kt = (s) * BK; \
    __nv_bfloat16* ap = As + ((s) & 3) * STAGEF; \
    __nv_bfloat16* bp = Bs + ((s) & 3) * STAGEF; \
    CP16(s2u(ap + c0r * LDS_S + c0c), Ag + (size_t)c0r * KEXT + kt + c0c); \
    CP16(s2u(ap + c1r * LDS_S + c1c), Ag + (size_t)c1r * KEXT + kt + c1c); \
    CP16(s2u(bp + c0r * LDS_S + c0c), Bg + (size_t)c0r * KEXT + kt + c0c); \
    CP16(s2u(bp + c1r * LDS_S + c1c), Bg + (size_t)c1r * KEXT + kt + c1c); \
    CP_COMMIT(); \
} while (0)

    const int wm = wid & 1, wn = wid >> 1;
    const int Am = wm * 64, Bn = wn * 32;
    const int a_row = lane & 15;
    const int a_ko  = (lane >> 4) << 3;
    const int b_n   = ((lane >> 4) << 3) + (lane & 7);
    const int b_ko  = ((lane >> 3) & 1) << 3;

    float d[4][4][4];
#pragma unroll
    for (int i = 0; i < 4; i++)
#pragma unroll
        for (int j = 0; j < 4; j++)
#pragma unroll
            for (int e = 0; e < 4; e++) d[i][j][e] = 0.f;

    LOADSTAGE(0);
    LOADSTAGE(1);
    LOADSTAGE(2);

    for (int s = 0; s < NSTG; s++) {
        if (s < NSTG - 2)       CP_WAIT(2);
        else if (s == NSTG - 2) CP_WAIT(1);
        else                    CP_WAIT(0);
        __syncthreads();

        const __nv_bfloat16* abuf = As + (s & 3) * STAGEF;
        const __nv_bfloat16* bbuf = Bs + (s & 3) * STAGEF;
#pragma unroll
        for (int kk = 0; kk < BK; kk += 16) {
            uint32_t a[4][4];
#pragma unroll
            for (int mi = 0; mi < 4; mi++) {
                const uint32_t ad =
                    s2u(abuf + (Am + mi * 16 + a_row) * LDS_S + kk + a_ko);
                LDSM4(a[mi][0], a[mi][1], a[mi][2], a[mi][3], ad);
            }
            uint32_t b[2][4];
#pragma unroll
            for (int nb = 0; nb < 2; nb++) {
                const uint32_t bd =
                    s2u(bbuf + (Bn + nb * 16 + b_n) * LDS_S + kk + b_ko);
                LDSM4(b[nb][0], b[nb][1], b[nb][2], b[nb][3], bd);
            }
#pragma unroll
            for (int mi = 0; mi < 4; mi++)
#pragma unroll
                for (int nj = 0; nj < 4; nj++)
                    MMA16816(d[mi][nj], a[mi], b[nj >> 1][(nj & 1) * 2],
                             b[nj >> 1][(nj & 1) * 2 + 1]);
        }
        if (s + 3 < NSTG) LOADSTAGE(s + 3);
    }
#undef LOADSTAGE

    const int erow = lane >> 2;
    const int ecol = (lane & 3) << 1;
#pragma unroll
    for (int mi = 0; mi < 4; mi++) {
#pragma unroll
        for (int nj = 0; nj < 4; nj++) {
            const int col = colBase + Bn + nj * 8 + ecol;
            const float b0 = bias[col], b1 = bias[col + 1];
#pragma unroll
            for (int half = 0; half < 2; half++) {
                const int r = rowBase + Am + mi * 16 + erow + half * 8;
                float2 v;
                v.x = d[mi][nj][half * 2 + 0] + b0;
                v.y = d[mi][nj][half * 2 + 1] + b1;
                if (MODE == 0) {
                    const int sel = col >> 8, h = (col >> 5) & 7, dd = col & 31;
                    const int bb = r / NTOK, nn = r - bb * NTOK;
                    float* dst = (sel == 0) ? g_q : (sel == 1) ? g_k : g_v;
                    if (sel == 0) { v.x *= QSCALE; v.y *= QSCALE; }
                    *(float2*)&dst[(((size_t)bb * NH + h) * NTOK + nn) * HDIM + dd] = v;
                } else {
                    *(float2*)&out[(size_t)r * CDIM + col] = v;
                }
            }
        }
    }
}

// ---------------- HMMA flash attention (online softmax, 2 chunks) ----------------
// CTA = one (b,h); 4 warps; n16 tiles processed in chunks of 7+6 with running
// max/sum so live S registers halve -> no spills at 3 CTAs/SM.
#define AT_S   72                          // smem row stride (bf16), conflict-free
#define AROWS  208
#define ASMEM_BYTES (2 * AROWS * AT_S * 2)  // 59904

__global__ __launch_bounds__(128, 3) void attn_mma(
    const float* __restrict__ mask)
{
    extern __shared__ __align__(16) __nv_bfloat16 smb[];
    __nv_bfloat16* Ks = smb;
    __nv_bfloat16* Vs = smb + AROWS * AT_S;

    const int tid = threadIdx.x, lane = tid & 31, wid = tid >> 5;
    const int bh = blockIdx.x, b = bh >> 3, h = bh & 7;
    const size_t base = (size_t)bh * (NTOK * HDIM);

    // zero pad rows 196..207 (cols 0..63 used by ldmatrix)
    for (int i = tid; i < 12 * 64; i += 128) {
        const int r = 196 + (i >> 6), c = i & 63;
        const __nv_bfloat16 z = __float2bfloat16(0.f);
        Ks[r * AT_S + c] = z; Vs[r * AT_S + c] = z;
    }
    // load + split k/v
    for (int i = tid; i < NTOK * HDIM; i += 128) {
        const int r = i >> 5, d = i & 31;
        const float k = g_k[base + i], v = g_v[base + i];
        const __nv_bfloat16 kh = __float2bfloat16(k);
        const __nv_bfloat16 vh = __float2bfloat16(v);
        Ks[r * AT_S + d] = kh; Ks[r * AT_S + 32 + d] = __float2bfloat16(k - __bfloat162float(kh));
        Vs[r * AT_S + d] = vh; Vs[r * AT_S + 32 + d] = __float2bfloat16(v - __bfloat162float(vh));
    }
    __syncthreads();

    const uint32_t Ksu = s2u(Ks), Vsu = s2u(Vs);
    const float* bmB = g_bm + h * (NTOK * NTOK);
    const float* mkB = mask + (size_t)(b & 63) * (NTOK * NTOK);

    const int b_n   = ((lane >> 4) << 3) + (lane & 7);
    const int b_ko  = ((lane >> 3) & 1) << 3;

    for (int mt = wid; mt < 13; mt += 4) {
        const int mb = mt * 16;

        // Q A-fragments built directly from g_q (canonical m16k16 layout)
        uint32_t aq[4][4];
        {
            const int rq0 = min(mb + (lane >> 2), 195);
            const int rq1 = min(mb + (lane >> 2) + 8, 195);
            const int cq = (lane & 3) << 1;
            const float* qp0 = g_q + base + rq0 * HDIM + cq;
            const float* qp1 = g_q + base + rq1 * HDIM + cq;
#pragma unroll
            for (int g = 0; g < 2; g++) {
                split2(*(const float2*)(qp0 + g * 16),     aq[g][0], aq[g + 2][0]);
                split2(*(const float2*)(qp1 + g * 16),     aq[g][1], aq[g + 2][1]);
                split2(*(const float2*)(qp0 + g * 16 + 8), aq[g][2], aq[g + 2][2]);
                split2(*(const float2*)(qp1 + g * 16 + 8), aq[g][3], aq[g + 2][3]);
            }
        }

        const int r0 = mb + (lane >> 2), r1 = r0 + 8;
        const int r0e = min(r0, 195), r1e = min(r1, 195);

        float O[4][4];
#pragma unroll
        for (int j = 0; j < 4; j++)
#pragma unroll
            for (int e = 0; e < 4; e++) O[j][e] = 0.f;
        float M0 = -1e30f, M1 = -1e30f, SU0 = 0.f, SU1 = 0.f;

// one online-softmax chunk over NT n16-tiles starting at tile T0
#define CHUNK(T0, NT) do { \
    float S[2 * NT][4]; \
    _Pragma("unroll") for (int j = 0; j < 2 * NT; j++) \
        _Pragma("unroll") for (int e = 0; e < 4; e++) S[j][e] = 0.f; \
    _Pragma("unroll") \
    for (int n16 = 0; n16 < NT; n16++) { \
        const int nb = (T0 + n16) * 16; \
        uint32_t bk[4][4]; \
        _Pragma("unroll") for (int kt = 0; kt < 4; kt++) { \
            const uint32_t bd = Ksu + ((nb + b_n) * AT_S + kt * 16 + b_ko) * 2; \
            LDSM4(bk[kt][0], bk[kt][1], bk[kt][2], bk[kt][3], bd); \
        } \
        const int pa[6] = {0, 1, 2, 3, 0, 1}; \
        const int pb[6] = {0, 1, 0, 1, 2, 3}; \
        _Pragma("unroll") for (int t = 0; t < 6; t++) { \
            MMA16816(S[2 * n16],     aq[pa[t]], bk[pb[t]][0], bk[pb[t]][1]); \
            MMA16816(S[2 * n16 + 1], aq[pa[t]], bk[pb[t]][2], bk[pb[t]][3]); \
        } \
    } \
    _Pragma("unroll") \
    for (int j = 0; j < 2 * NT; j++) { \
        const int c = (2 * T0 + j) * 8 + ((lane & 3) << 1); \
        const int ce = min(c, 194); \
        const float2 b0v = *(const float2*)(bmB + r0e * NTOK + ce); \
        const float2 b1v = *(const float2*)(bmB + r1e * NTOK + ce); \
        const float2 m0v = *(const float2*)(mkB + (size_t)r0e * NTOK + ce); \
        const float2 m1v = *(const float2*)(mkB + (size_t)r1e * NTOK + ce); \
        S[j][0] += b0v.x + m0v.x; S[j][1] += b0v.y + m0v.y; \
        S[j][2] += b1v.x + m1v.x; S[j][3] += b1v.y + m1v.y; \
        if (c >= NTOK) { S[j][0] = S[j][1] = S[j][2] = S[j][3] = -1e9f; } \
    } \
    float cm0 = -1e30f, cm1 = -1e30f; \
    _Pragma("unroll") for (int j = 0; j < 2 * NT; j++) { \
        cm0 = fmaxf(cm0, fmaxf(S[j][0], S[j][1])); \
        cm1 = fmaxf(cm1, fmaxf(S[j][2], S[j][3])); \
    } \
    cm0 = fmaxf(cm0, __shfl_xor_sync(0xffffffffu, cm0, 1)); \
    cm0 = fmaxf(cm0, __shfl_xor_sync(0xffffffffu, cm0, 2)); \
    cm1 = fmaxf(cm1, __shfl_xor_sync(0xffffffffu, cm1, 1)); \
    cm1 = fmaxf(cm1, __shfl_xor_sync(0xffffffffu, cm1, 2)); \
    const float Mn0 = fmaxf(M0, cm0), Mn1 = fmaxf(M1, cm1); \
    const float rf0 = __expf(M0 - Mn0), rf1 = __expf(M1 - Mn1); \
    M0 = Mn0; M1 = Mn1; \
    float cs0 = 0.f, cs1 = 0.f; \
    _Pragma("unroll") for (int j = 0; j < 2 * NT; j++) { \
        S[j][0] = __expf(S[j][0] - M0); S[j][1] = __expf(S[j][1] - M0); \
        S[j][2] = __expf(S[j][2] - M1); S[j][3] = __expf(S[j][3] - M1); \
        cs0 += S[j][0] + S[j][1]; cs1 += S[j][2] + S[j][3]; \
    } \
    cs0 += __shfl_xor_sync(0xffffffffu, cs0, 1); \
    cs0 += __shfl_xor_sync(0xffffffffu, cs0, 2); \
    cs1 += __shfl_xor_sync(0xffffffffu, cs1, 1); \
    cs1 += __shfl_xor_sync(0xffffffffu, cs1, 2); \
    SU0 = SU0 * rf0 + cs0; SU1 = SU1 * rf1 + cs1; \
    _Pragma("unroll") for (int j = 0; j < 4; j++) { \
        O[j][0] *= rf0; O[j][1] *= rf0; O[j][2] *= rf1; O[j][3] *= rf1; \
    } \
    _Pragma("unroll") \
    for (int kt = 0; kt < NT; kt++) { \
        uint32_t ph[4], pl[4]; \
        _Pragma("unroll") for (int half = 0; half < 2; half++) { \
            const float e0 = S[2 * kt + half][0], e1 = S[2 * kt + half][1]; \
            const float e2 = S[2 * kt + half][2], e3 = S[2 * kt + half][3]; \
            const uint32_t h01 = bfpack(e0, e1); \
            const uint32_t h23 = bfpack(e2, e3); \
            const float q0 = __uint_as_float(h01 << 16); \
            const float q1 = __uint_as_float(h01 & 0xffff0000u); \
            const float q2 = __uint_as_float(h23 << 16); \
            const float q3 = __uint_as_float(h23 & 0xffff0000u); \
            ph[half * 2 + 0] = h01; ph[half * 2 + 1] = h23; \
            pl[half * 2 + 0] = bfpack(e0 - q0, e1 - q1); \
            pl[half * 2 + 1] = bfpack(e2 - q2, e3 - q3); \
        } \
        uint32_t vh[2][4], vl[2][4]; \
        _Pragma("unroll") for (int g = 0; g < 2; g++) { \
            const uint32_t vda = \
                Vsu + (((T0 + kt) * 16 + (lane & 15)) * AT_S + g * 16 + ((lane >> 4) << 3)) * 2; \
            LDSM4T(vh[g][0], vh[g][1], vh[g][2], vh[g][3], vda); \
            LDSM4T(vl[g][0], vl[g][1], vl[g][2], vl[g][3], vda + 64); \
        } \
        _Pragma("unroll") for (int g = 0; g < 2; g++) { \
            MMA16816(O[g * 2 + 0], ph, vh[g][0], vh[g][1]); \
            MMA16816(O[g * 2 + 1], ph, vh[g][2], vh[g][3]); \
            MMA16816(O[g * 2 + 0], pl, vh[g][0], vh[g][1]); \
            MMA16816(O[g * 2 + 1], pl, vh[g][2], vh[g][3]); \
            MMA16816(O[g * 2 + 0], ph, vl[g][0], vl[g][1]); \
            MMA16816(O[g * 2 + 1], ph, vl[g][2], vl[g][3]); \
        } \
    } \
} while (0)

        CHUNK(0, 7);
        CHUNK(7, 6);
#undef CHUNK

        const float inv0 = 1.0f / SU0, inv1 = 1.0f / SU1;

        // store split-bf16 directly into g_ob (fused conversion)
        const int dcol = (lane & 3) << 1;
        if (r0 < NTOK) {
            __nv_bfloat16* op = g_ob + ((size_t)b * NTOK + r0) * KEXT + h * HDIM + dcol;
#pragma unroll
            for (int j = 0; j < 4; j++) {
                const float v0 = O[j][0] * inv0, v1 = O[j][1] * inv0;
                uint32_t hi, lo;
                split2(make_float2(v0, v1), hi, lo);
                *(uint32_t*)(op + j * 8)       = hi;
                *(uint32_t*)(op + j * 8 + 256) = lo;
                *(uint32_t*)(op + j * 8 + 512) = hi;
            }
        }
        if (r1 < NTOK) {
            __nv_bfloat16* op = g_ob + ((size_t)b * NTOK + r1) * KEXT + h * HDIM + dcol;
#pragma unroll
            for (int j = 0; j < 4; j++) {
                const float v0 = O[j][2] * inv1, v1 = O[j][3] * inv1;
                uint32_t hi, lo;
                split2(make_float2(v0, v1), hi, lo);
                *(uint32_t*)(op + j * 8)       = hi;
                *(uint32_t*)(op + j * 8 + 256) = lo;
                *(uint32_t*)(op + j * 8 + 512) = hi;
            }
        }
    }
}

// ---------------------------------------------------------------------------
extern "C" void kernel_launch(void* const* d_in, const int* in_sizes, int n_in,
                              void* d_out, int out_size)
{
    const float* x          = (const float*)d_in[0];
    const float* mask       = (const float*)d_in[1];
    const float* qkv_w      = (const float*)d_in[2];
    const float* qkv_b      = (const float*)d_in[3];
    const float* proj_w     = (const float*)d_in[4];
    const float* proj_b     = (const float*)d_in[5];
    const float* bias_table = (const float*)d_in[6];
    const int*   rel_index  = (const int*)d_in[7];
    float* out = (float*)d_out;

    cudaFuncSetAttribute(attn_mma,
                         cudaFuncAttributeMaxDynamicSharedMemorySize, ASMEM_BYTES);
    cudaFuncSetAttribute(hmma_gemm<0>,
                         cudaFuncAttributeMaxDynamicSharedMemorySize, GSMEM);
    cudaFuncSetAttribute(hmma_gemm<1>,
                         cudaFuncAttributeMaxDynamicSharedMemorySize, GSMEM);

    __nv_bfloat16 *xb, *wq, *wp;
    cudaGetSymbolAddress((void**)&xb, g_xb);
    cudaGetSymbolAddress((void**)&wq, g_wq);
    cudaGetSymbolAddress((void**)&wp, g_wp);

    // 1) split-bf16 conversions + bias gather precompute
    conv_act<<<MROWS * 64 / 256, 256>>>(x, xb);
    conv_wgt<<<768 * 64 / 256, 256>>>(qkv_w, wq);
    conv_wgt<<<256 * 64 / 256, 256>>>(proj_w, wp);
    bias_pre<<<(NTOK * NTOK + 255) / 256, 256>>>(bias_table, rel_index);
    // 2) QKV projection (HMMA): N tiles 0..5 -> q (scaled), k, v
    hmma_gemm<0><<<dim3(6, MROWS / 128), 256, GSMEM>>>(qkv_b, nullptr);
    // 3) HMMA flash attention -> g_ob (split bf16, fused)
    attn_mma<<<B__ * NH, 128, ASMEM_BYTES>>>(mask);
    // 4) output projection (HMMA)
    hmma_gemm<1><<<dim3(2, MROWS / 128), 256, GSMEM>>>(proj_b, out);
}